// round 9
// baseline (speedup 1.0000x reference)
#include <cuda_runtime.h>
#include <cuda_bf16.h>
#include <math.h>
#include <stdint.h>

// Problem constants
#define PB  2
#define PS  2048
#define PD  4096
#define PH  32
#define PKVH 8
#define PHD 128
#define ROWS (PB*PS)            // 4096 tokens
#define QCOLS (PH*PHD)          // 4096
#define KVCOLS (PKVH*PHD)       // 1024

// ---------------------------------------------------------------------------
// Scratch (static device allocations)
// ---------------------------------------------------------------------------
__device__ float g_Q[(size_t)ROWS * QCOLS];   // 64 MB
__device__ float g_K[(size_t)ROWS * KVCOLS];  // 16 MB
__device__ float g_V[(size_t)ROWS * KVCOLS];  // 16 MB
__device__ float g_O[(size_t)ROWS * QCOLS];   // 64 MB

// ---------------------------------------------------------------------------
// TF32 helpers
// ---------------------------------------------------------------------------
__device__ __forceinline__ uint32_t f2tf(float x) {
    uint32_t r;
    asm("cvt.rna.tf32.f32 %0, %1;" : "=r"(r) : "f"(x));
    return r;
}

__device__ __forceinline__ void mma_tf32(float c[4], const uint32_t a[4],
                                         const uint32_t b[2]) {
    asm volatile(
        "mma.sync.aligned.m16n8k8.row.col.f32.tf32.tf32.f32 "
        "{%0,%1,%2,%3}, {%4,%5,%6,%7}, {%8,%9}, {%0,%1,%2,%3};"
        : "+f"(c[0]), "+f"(c[1]), "+f"(c[2]), "+f"(c[3])
        : "r"(a[0]), "r"(a[1]), "r"(a[2]), "r"(a[3]),
          "r"(b[0]), "r"(b[1]));
}

// ---------------------------------------------------------------------------
// TF32 tensor-core GEMM: C[M,N] = A[M,K] @ B[K,N], row-major fp32 in/out.
// 128x128x32 CTA tile, 8 warps (2x4), 64x32 warp tile, m16n8k8 tf32.
// A smem is FRAGMENT-MAJOR: each thread's 4 A-regs for a 16x8 block are one
// contiguous uint4 -> LDS.128, conflict-free. B smem row-major padded
// (bank = (8k+n)%32 permutation -> conflict-free scalar loads).
// Epilogue template: EPI=0 plain fp32, EPI=1 RoPE+scale+tf32-round,
// EPI=2 tf32-round only.
// M,N %128==0, K %32==0.
// ---------------------------------------------------------------------------
#define TBM 128
#define TBN 128
#define TBK 32
#define BPAD 136                    // B row stride (136%32=8 -> permutation)
#define ABUF 4096                   // u32 per A buffer (8 mt * 4 kf * 32 * 4)
#define BBUF (TBK*BPAD)             // u32 per B buffer
#define GSMEM ((2*ABUF + 2*BBUF) * 4)

template<int EPI>
__global__ __launch_bounds__(256)
void tf32gemm(const float* __restrict__ A, const float* __restrict__ B,
              float* __restrict__ C, int M, int N, int K,
              const float* __restrict__ fc, const float* __restrict__ fs,
              float scale) {
    extern __shared__ uint32_t smg[];
    uint32_t* As = smg;             // [2][ABUF] fragment-major
    uint32_t* Bs = smg + 2 * ABUF;  // [2][TBK][BPAD]

    const int tid  = threadIdx.x;
    const int lane = tid & 31;
    const int wid  = tid >> 5;
    const int gID  = lane >> 2;
    const int tig  = lane & 3;
    const int wr   = wid >> 2;      // 0..1
    const int wc   = wid & 3;       // 0..3
    const int n0   = wc * 32;
    const int rBase = blockIdx.y * TBM;
    const int cBase = blockIdx.x * TBN;

    // A staging decomposition: 4 float4 per thread over 128 rows x 8 f4-cols
    int a_row[4], a_kq[4], a_off[4], b_kr[4], b_nq[4];
#pragma unroll
    for (int r = 0; r < 4; r++) {
        int id = tid + r * 256;
        a_row[r] = id >> 3;
        a_kq[r]  = (id & 7) * 4;
        // fragment-major store base: block*(128) + reg; lane filled per element
        int blk = ((a_row[r] >> 4) * 4 + (a_kq[r] >> 3)) * 128;
        int reg = ((a_row[r] >> 3) & 1) | (((a_kq[r] >> 2) & 1) << 1);
        a_off[r] = blk + (a_row[r] & 7) * 16 + reg;   // + e*4 per element
        b_kr[r] = id >> 5;
        b_nq[r] = (id & 31) * 4;
    }

    float acc[4][4][4];
#pragma unroll
    for (int mf = 0; mf < 4; mf++)
#pragma unroll
        for (int nf = 0; nf < 4; nf++)
#pragma unroll
            for (int r = 0; r < 4; r++) acc[mf][nf][r] = 0.f;

    float4 pa[4], pb[4];

    // ---- prologue: tile 0 gmem -> regs -> smem[0] ----
#pragma unroll
    for (int r = 0; r < 4; r++) {
        pa[r] = *(const float4*)(A + (size_t)(rBase + a_row[r]) * K + a_kq[r]);
        pb[r] = *(const float4*)(B + (size_t)b_kr[r] * N + cBase + b_nq[r]);
    }
#pragma unroll
    for (int r = 0; r < 4; r++) {
        uint32_t* p = As + a_off[r];
        p[0]  = f2tf(pa[r].x); p[4]  = f2tf(pa[r].y);
        p[8]  = f2tf(pa[r].z); p[12] = f2tf(pa[r].w);
        uint4 bv = make_uint4(f2tf(pb[r].x), f2tf(pb[r].y),
                              f2tf(pb[r].z), f2tf(pb[r].w));
        *(uint4*)(Bs + b_kr[r] * BPAD + b_nq[r]) = bv;
    }
    __syncthreads();

    const int nIter = K / TBK;
    for (int it = 0; it < nIter; it++) {
        const int bufA = (it & 1) * ABUF;
        const int bufB = (it & 1) * BBUF;
        const bool more = (it + 1 < nIter);
        if (more) {
            const int k0 = (it + 1) * TBK;
#pragma unroll
            for (int r = 0; r < 4; r++) {
                pa[r] = *(const float4*)(A + (size_t)(rBase + a_row[r]) * K + k0 + a_kq[r]);
                pb[r] = *(const float4*)(B + (size_t)(k0 + b_kr[r]) * N + cBase + b_nq[r]);
            }
        }

#pragma unroll
        for (int kf = 0; kf < 4; kf++) {
            uint32_t aF[4][4];
#pragma unroll
            for (int mf = 0; mf < 4; mf++) {
                uint4 q = *(const uint4*)(As + bufA +
                            (((wr * 4 + mf) * 4 + kf) * 128) + lane * 4);
                aF[mf][0] = q.x; aF[mf][1] = q.y; aF[mf][2] = q.z; aF[mf][3] = q.w;
            }
            uint32_t bF[4][2];
            const uint32_t* bk0 = Bs + bufB + (kf * 8 + tig) * BPAD;
            const uint32_t* bk1 = bk0 + 4 * BPAD;
#pragma unroll
            for (int nf = 0; nf < 4; nf++) {
                const int nc = n0 + nf * 8 + gID;
                bF[nf][0] = bk0[nc];
                bF[nf][1] = bk1[nc];
            }
#pragma unroll
            for (int mf = 0; mf < 4; mf++)
#pragma unroll
                for (int nf = 0; nf < 4; nf++)
                    mma_tf32(acc[mf][nf], aF[mf], bF[nf]);
        }

        if (more) {
            const int nbA = (bufA ^ ABUF);
            const int nbB = (bufB ^ BBUF);
#pragma unroll
            for (int r = 0; r < 4; r++) {
                uint32_t* p = As + nbA + a_off[r];
                p[0]  = f2tf(pa[r].x); p[4]  = f2tf(pa[r].y);
                p[8]  = f2tf(pa[r].z); p[12] = f2tf(pa[r].w);
                uint4 bv = make_uint4(f2tf(pb[r].x), f2tf(pb[r].y),
                                      f2tf(pb[r].z), f2tf(pb[r].w));
                *(uint4*)(Bs + nbB + b_kr[r] * BPAD + b_nq[r]) = bv;
            }
        }
        __syncthreads();
    }

    // ---- epilogue ----
#pragma unroll
    for (int mf = 0; mf < 4; mf++) {
#pragma unroll
        for (int nf = 0; nf < 4; nf++) {
            const int row = rBase + wr * 64 + mf * 16 + gID;
            const int col = cBase + n0 + nf * 8 + tig * 2;
            float* p0 = C + (size_t)row * N + col;
            float* p1 = C + (size_t)(row + 8) * N + col;
            if (EPI == 0) {
                *(float2*)p0 = make_float2(acc[mf][nf][0], acc[mf][nf][1]);
                *(float2*)p1 = make_float2(acc[mf][nf][2], acc[mf][nf][3]);
            } else if (EPI == 2) {
                *(uint2*)p0 = make_uint2(f2tf(acc[mf][nf][0]), f2tf(acc[mf][nf][1]));
                *(uint2*)p1 = make_uint2(f2tf(acc[mf][nf][2]), f2tf(acc[mf][nf][3]));
            } else {
                // RoPE pair (even,odd) = (c0,c1); fold scale; tf32-round.
                const int pr = (col & (PHD - 1)) >> 1;
                const int s0 = row & (PS - 1);
                const int s1 = (row + 8) & (PS - 1);
                const float c0 = fc[s0 * 64 + pr], sn0 = fs[s0 * 64 + pr];
                const float c1 = fc[s1 * 64 + pr], sn1 = fs[s1 * 64 + pr];
                const float r0 = (acc[mf][nf][0] * c0 - acc[mf][nf][1] * sn0) * scale;
                const float i0 = (acc[mf][nf][0] * sn0 + acc[mf][nf][1] * c0) * scale;
                const float r1 = (acc[mf][nf][2] * c1 - acc[mf][nf][3] * sn1) * scale;
                const float i1 = (acc[mf][nf][2] * sn1 + acc[mf][nf][3] * c1) * scale;
                *(uint2*)p0 = make_uint2(f2tf(r0), f2tf(i0));
                *(uint2*)p1 = make_uint2(f2tf(r1), f2tf(i1));
            }
        }
    }
}

// ---------------------------------------------------------------------------
// Tensor-core causal flash attention (unchanged from round 8).
// ---------------------------------------------------------------------------
#define BQ 128
#define BK 64
#define KPAD 132
#define VPAD 136
#define PPAD 68

__global__ __launch_bounds__(256, 1)
void flash_attn_tc(const float* __restrict__ Q, const float* __restrict__ K,
                   const float* __restrict__ V, float* __restrict__ O) {
    extern __shared__ float sm[];
    float* Ks = sm;                    // [64][132]
    float* Vs = Ks + BK * KPAD;        // [64][136]
    float* Ps = Vs + BK * VPAD;        // [128][68]

    const int tid  = threadIdx.x;
    const int lane = tid & 31;
    const int wid  = tid >> 5;
    const int gID  = lane >> 2;
    const int tig  = lane & 3;
    const int qb   = blockIdx.x;
    const int h    = blockIdx.y;
    const int b    = blockIdx.z;
    const int kvh  = h >> 2;
    const int m0   = wid * 16;
    const int qRow0 = b * PS + qb * BQ;

    uint32_t aQ[16][4];
    {
        const float* Qg = Q + (size_t)(qRow0 + m0) * QCOLS + h * PHD;
#pragma unroll
        for (int kb = 0; kb < 16; kb++) {
            const int c = kb * 8 + tig;
            aQ[kb][0] = __float_as_uint(Qg[(size_t)gID       * QCOLS + c    ]);
            aQ[kb][1] = __float_as_uint(Qg[(size_t)(gID + 8) * QCOLS + c    ]);
            aQ[kb][2] = __float_as_uint(Qg[(size_t)gID       * QCOLS + c + 4]);
            aQ[kb][3] = __float_as_uint(Qg[(size_t)(gID + 8) * QCOLS + c + 4]);
        }
    }

    float oAcc[16][4];
#pragma unroll
    for (int nf = 0; nf < 16; nf++)
#pragma unroll
        for (int r = 0; r < 4; r++) oAcc[nf][r] = 0.f;
    float m_i[2] = {-1e30f, -1e30f};
    float l_i[2] = {0.f, 0.f};

    const int nkt = 2 * qb + 2;
    for (int kt = 0; kt < nkt; kt++) {
        __syncthreads();
        {
            const int kRow0 = b * PS + kt * BK;
            const float* Kg = K + (size_t)kRow0 * KVCOLS + kvh * PHD;
            const float* Vg = V + (size_t)kRow0 * KVCOLS + kvh * PHD;
#pragma unroll
            for (int r = 0; r < 8; r++) {
                int t  = tid + r * 256;
                int j  = t >> 5;
                int c4 = (t & 31) * 4;
                *(float4*)(&Ks[j * KPAD + c4]) =
                    *(const float4*)(Kg + (size_t)j * KVCOLS + c4);
                *(float4*)(&Vs[j * VPAD + c4]) =
                    *(const float4*)(Vg + (size_t)j * KVCOLS + c4);
            }
        }
        __syncthreads();

        float sAcc[8][4];
#pragma unroll
        for (int nf = 0; nf < 8; nf++)
#pragma unroll
            for (int r = 0; r < 4; r++) sAcc[nf][r] = 0.f;

#pragma unroll
        for (int kb = 0; kb < 16; kb++) {
            const int kc = kb * 8 + tig;
#pragma unroll
            for (int nf = 0; nf < 8; nf++) {
                uint32_t bK[2];
                bK[0] = __float_as_uint(Ks[(nf * 8 + gID) * KPAD + kc    ]);
                bK[1] = __float_as_uint(Ks[(nf * 8 + gID) * KPAD + kc + 4]);
                mma_tf32(sAcc[nf], aQ[kb], bK);
            }
        }

        if (kt >= 2 * qb) {
            const int r0 = qb * BQ + m0 + gID;
            const int r1 = r0 + 8;
            const int cb = kt * BK + 2 * tig;
#pragma unroll
            for (int nf = 0; nf < 8; nf++) {
                const int c0 = cb + nf * 8;
                if (c0     > r0) sAcc[nf][0] = -1e30f;
                if (c0 + 1 > r0) sAcc[nf][1] = -1e30f;
                if (c0     > r1) sAcc[nf][2] = -1e30f;
                if (c0 + 1 > r1) sAcc[nf][3] = -1e30f;
            }
        }

        float mx0 = -1e30f, mx1 = -1e30f;
#pragma unroll
        for (int nf = 0; nf < 8; nf++) {
            mx0 = fmaxf(mx0, fmaxf(sAcc[nf][0], sAcc[nf][1]));
            mx1 = fmaxf(mx1, fmaxf(sAcc[nf][2], sAcc[nf][3]));
        }
        mx0 = fmaxf(mx0, __shfl_xor_sync(0xffffffffu, mx0, 1));
        mx0 = fmaxf(mx0, __shfl_xor_sync(0xffffffffu, mx0, 2));
        mx1 = fmaxf(mx1, __shfl_xor_sync(0xffffffffu, mx1, 1));
        mx1 = fmaxf(mx1, __shfl_xor_sync(0xffffffffu, mx1, 2));

        const float mn0 = fmaxf(m_i[0], mx0);
        const float mn1 = fmaxf(m_i[1], mx1);
        const float al0 = __expf(m_i[0] - mn0);
        const float al1 = __expf(m_i[1] - mn1);

        float rs0 = 0.f, rs1 = 0.f;
#pragma unroll
        for (int nf = 0; nf < 8; nf++) {
            sAcc[nf][0] = __expf(sAcc[nf][0] - mn0);
            sAcc[nf][1] = __expf(sAcc[nf][1] - mn0);
            sAcc[nf][2] = __expf(sAcc[nf][2] - mn1);
            sAcc[nf][3] = __expf(sAcc[nf][3] - mn1);
            rs0 += sAcc[nf][0] + sAcc[nf][1];
            rs1 += sAcc[nf][2] + sAcc[nf][3];
        }
        rs0 += __shfl_xor_sync(0xffffffffu, rs0, 1);
        rs0 += __shfl_xor_sync(0xffffffffu, rs0, 2);
        rs1 += __shfl_xor_sync(0xffffffffu, rs1, 1);
        rs1 += __shfl_xor_sync(0xffffffffu, rs1, 2);

        l_i[0] = l_i[0] * al0 + rs0;
        l_i[1] = l_i[1] * al1 + rs1;
        m_i[0] = mn0;
        m_i[1] = mn1;

#pragma unroll
        for (int nf = 0; nf < 16; nf++) {
            oAcc[nf][0] *= al0; oAcc[nf][1] *= al0;
            oAcc[nf][2] *= al1; oAcc[nf][3] *= al1;
        }

#pragma unroll
        for (int nf = 0; nf < 8; nf++) {
            const int col = nf * 8 + 2 * tig;
            *(uint2*)(&Ps[(m0 + gID    ) * PPAD + col]) =
                make_uint2(f2tf(sAcc[nf][0]), f2tf(sAcc[nf][1]));
            *(uint2*)(&Ps[(m0 + gID + 8) * PPAD + col]) =
                make_uint2(f2tf(sAcc[nf][2]), f2tf(sAcc[nf][3]));
        }
        __syncwarp();

#pragma unroll
        for (int kb = 0; kb < 8; kb++) {
            const int kc = kb * 8 + tig;
            uint32_t aP[4];
            aP[0] = __float_as_uint(Ps[(m0 + gID    ) * PPAD + kc    ]);
            aP[1] = __float_as_uint(Ps[(m0 + gID + 8) * PPAD + kc    ]);
            aP[2] = __float_as_uint(Ps[(m0 + gID    ) * PPAD + kc + 4]);
            aP[3] = __float_as_uint(Ps[(m0 + gID + 8) * PPAD + kc + 4]);
#pragma unroll
            for (int nf = 0; nf < 16; nf++) {
                uint32_t bV[2];
                bV[0] = __float_as_uint(Vs[(kc    ) * VPAD + nf * 8 + gID]);
                bV[1] = __float_as_uint(Vs[(kc + 4) * VPAD + nf * 8 + gID]);
                mma_tf32(oAcc[nf], aP, bV);
            }
        }
        __syncwarp();
    }

    const float il0 = 1.f / l_i[0];
    const float il1 = 1.f / l_i[1];
    float* Og = O + (size_t)(qRow0 + m0) * QCOLS + h * PHD;
#pragma unroll
    for (int nf = 0; nf < 16; nf++) {
        const int col = nf * 8 + 2 * tig;
        *(float2*)(Og + (size_t)gID       * QCOLS + col) =
            make_float2(oAcc[nf][0] * il0, oAcc[nf][1] * il0);
        *(float2*)(Og + (size_t)(gID + 8) * QCOLS + col) =
            make_float2(oAcc[nf][2] * il1, oAcc[nf][3] * il1);
    }
}

// ---------------------------------------------------------------------------
// Launch
// ---------------------------------------------------------------------------
extern "C" void kernel_launch(void* const* d_in, const int* in_sizes, int n_in,
                              void* d_out, int out_size) {
    (void)in_sizes; (void)n_in; (void)out_size;

    const float* x  = (const float*)d_in[0];   // [B,S,D]
    const float* fc = (const float*)d_in[1];   // [S, HD/2]
    const float* fs = (const float*)d_in[2];   // [S, HD/2]
    const float* Wq = (const float*)d_in[3];   // [D, H*HD]
    const float* Wk = (const float*)d_in[4];   // [D, KVH*HD]
    const float* Wv = (const float*)d_in[5];   // [D, KVH*HD]
    const float* Wo = (const float*)d_in[6];   // [H*HD, D]
    float* out = (float*)d_out;                // [B,S,D]

    float *Qb, *Kb, *Vb, *Ob;
    cudaGetSymbolAddress((void**)&Qb, g_Q);
    cudaGetSymbolAddress((void**)&Kb, g_K);
    cudaGetSymbolAddress((void**)&Vb, g_V);
    cudaGetSymbolAddress((void**)&Ob, g_O);

    cudaFuncSetAttribute(tf32gemm<0>, cudaFuncAttributeMaxDynamicSharedMemorySize, GSMEM);
    cudaFuncSetAttribute(tf32gemm<1>, cudaFuncAttributeMaxDynamicSharedMemorySize, GSMEM);
    cudaFuncSetAttribute(tf32gemm<2>, cudaFuncAttributeMaxDynamicSharedMemorySize, GSMEM);

    const float qscale = 0.08838834764831845f;   // 1/sqrt(128)

    // 1) QKV projections with fused RoPE/scale/round epilogues
    tf32gemm<1><<<dim3(QCOLS/TBN,  ROWS/TBM), 256, GSMEM>>>(
        x, Wq, Qb, ROWS, QCOLS,  PD, fc, fs, qscale);
    tf32gemm<1><<<dim3(KVCOLS/TBN, ROWS/TBM), 256, GSMEM>>>(
        x, Wk, Kb, ROWS, KVCOLS, PD, fc, fs, 1.0f);
    tf32gemm<2><<<dim3(KVCOLS/TBN, ROWS/TBM), 256, GSMEM>>>(
        x, Wv, Vb, ROWS, KVCOLS, PD, nullptr, nullptr, 1.0f);

    // 2) Tensor-core causal flash attention
    {
        size_t smem = (size_t)(BK * KPAD + BK * VPAD + BQ * PPAD) * sizeof(float);
        cudaFuncSetAttribute(flash_attn_tc,
                             cudaFuncAttributeMaxDynamicSharedMemorySize, (int)smem);
        flash_attn_tc<<<dim3(PS/BQ, PH, PB), 256, smem>>>(Qb, Kb, Vb, Ob);
    }

    // 3) Output projection -> d_out
    tf32gemm<0><<<dim3(PD/TBN, ROWS/TBM), 256, GSMEM>>>(
        Ob, Wo, out, ROWS, PD, QCOLS, nullptr, nullptr, 1.0f);
}

// round 10
// speedup vs baseline: 1.0011x; 1.0011x over previous
#include <cuda_runtime.h>
#include <cuda_bf16.h>
#include <math.h>
#include <stdint.h>

// Problem constants
#define PB  2
#define PS  2048
#define PD  4096
#define PH  32
#define PKVH 8
#define PHD 128
#define ROWS (PB*PS)            // 4096 tokens
#define QCOLS (PH*PHD)          // 4096
#define KVCOLS (PKVH*PHD)       // 1024

// ---------------------------------------------------------------------------
// Scratch (static device allocations)
// ---------------------------------------------------------------------------
__device__ float g_Q[(size_t)ROWS * QCOLS];   // 64 MB
__device__ float g_K[(size_t)ROWS * KVCOLS];  // 16 MB
__device__ float g_V[(size_t)ROWS * KVCOLS];  // 16 MB
__device__ float g_O[(size_t)ROWS * QCOLS];   // 64 MB

// ---------------------------------------------------------------------------
// TF32 helpers
// ---------------------------------------------------------------------------
__device__ __forceinline__ uint32_t f2tf(float x) {
    uint32_t r;
    asm("cvt.rna.tf32.f32 %0, %1;" : "=r"(r) : "f"(x));
    return r;
}

__device__ __forceinline__ void mma_tf32(float c[4], const uint32_t a[4],
                                         const uint32_t b[2]) {
    asm volatile(
        "mma.sync.aligned.m16n8k8.row.col.f32.tf32.tf32.f32 "
        "{%0,%1,%2,%3}, {%4,%5,%6,%7}, {%8,%9}, {%0,%1,%2,%3};"
        : "+f"(c[0]), "+f"(c[1]), "+f"(c[2]), "+f"(c[3])
        : "r"(a[0]), "r"(a[1]), "r"(a[2]), "r"(a[3]),
          "r"(b[0]), "r"(b[1]));
}

// ---------------------------------------------------------------------------
// TF32 tensor-core GEMM: C[M,N] = A[M,K] @ B[K,N], row-major fp32 in/out.
// 128x128x32 CTA tile, 8 warps (2x4), 64x32 warp tile, m16n8k8 tf32.
// A smem is FRAGMENT-MAJOR: each thread's 4 A-regs for a 16x8 block are one
// contiguous uint4 -> LDS.128, conflict-free. B smem row-major padded
// (bank = (8k+n)%32 permutation -> conflict-free scalar loads).
// Epilogue template: EPI=0 plain fp32, EPI=1 RoPE+scale+tf32-round,
// EPI=2 tf32-round only.
// M,N %128==0, K %32==0.
// ---------------------------------------------------------------------------
#define TBM 128
#define TBN 128
#define TBK 32
#define BPAD 136                    // B row stride (136%32=8 -> permutation)
#define ABUF 4096                   // u32 per A buffer (8 mt * 4 kf * 32 * 4)
#define BBUF (TBK*BPAD)             // u32 per B buffer
#define GSMEM ((2*ABUF + 2*BBUF) * 4)

template<int EPI>
__global__ __launch_bounds__(256)
void tf32gemm(const float* __restrict__ A, const float* __restrict__ B,
              float* __restrict__ C, int M, int N, int K,
              const float* __restrict__ fc, const float* __restrict__ fs,
              float scale) {
    extern __shared__ uint32_t smg[];
    uint32_t* As = smg;             // [2][ABUF] fragment-major
    uint32_t* Bs = smg + 2 * ABUF;  // [2][TBK][BPAD]

    const int tid  = threadIdx.x;
    const int lane = tid & 31;
    const int wid  = tid >> 5;
    const int gID  = lane >> 2;
    const int tig  = lane & 3;
    const int wr   = wid >> 2;      // 0..1
    const int wc   = wid & 3;       // 0..3
    const int n0   = wc * 32;
    const int rBase = blockIdx.y * TBM;
    const int cBase = blockIdx.x * TBN;

    // A staging decomposition: 4 float4 per thread over 128 rows x 8 f4-cols
    int a_row[4], a_kq[4], a_off[4], b_kr[4], b_nq[4];
#pragma unroll
    for (int r = 0; r < 4; r++) {
        int id = tid + r * 256;
        a_row[r] = id >> 3;
        a_kq[r]  = (id & 7) * 4;
        // fragment-major store base: block*(128) + reg; lane filled per element
        int blk = ((a_row[r] >> 4) * 4 + (a_kq[r] >> 3)) * 128;
        int reg = ((a_row[r] >> 3) & 1) | (((a_kq[r] >> 2) & 1) << 1);
        a_off[r] = blk + (a_row[r] & 7) * 16 + reg;   // + e*4 per element
        b_kr[r] = id >> 5;
        b_nq[r] = (id & 31) * 4;
    }

    float acc[4][4][4];
#pragma unroll
    for (int mf = 0; mf < 4; mf++)
#pragma unroll
        for (int nf = 0; nf < 4; nf++)
#pragma unroll
            for (int r = 0; r < 4; r++) acc[mf][nf][r] = 0.f;

    float4 pa[4], pb[4];

    // ---- prologue: tile 0 gmem -> regs -> smem[0] ----
#pragma unroll
    for (int r = 0; r < 4; r++) {
        pa[r] = *(const float4*)(A + (size_t)(rBase + a_row[r]) * K + a_kq[r]);
        pb[r] = *(const float4*)(B + (size_t)b_kr[r] * N + cBase + b_nq[r]);
    }
#pragma unroll
    for (int r = 0; r < 4; r++) {
        uint32_t* p = As + a_off[r];
        p[0]  = f2tf(pa[r].x); p[4]  = f2tf(pa[r].y);
        p[8]  = f2tf(pa[r].z); p[12] = f2tf(pa[r].w);
        uint4 bv = make_uint4(f2tf(pb[r].x), f2tf(pb[r].y),
                              f2tf(pb[r].z), f2tf(pb[r].w));
        *(uint4*)(Bs + b_kr[r] * BPAD + b_nq[r]) = bv;
    }
    __syncthreads();

    const int nIter = K / TBK;
    for (int it = 0; it < nIter; it++) {
        const int bufA = (it & 1) * ABUF;
        const int bufB = (it & 1) * BBUF;
        const bool more = (it + 1 < nIter);
        if (more) {
            const int k0 = (it + 1) * TBK;
#pragma unroll
            for (int r = 0; r < 4; r++) {
                pa[r] = *(const float4*)(A + (size_t)(rBase + a_row[r]) * K + k0 + a_kq[r]);
                pb[r] = *(const float4*)(B + (size_t)(k0 + b_kr[r]) * N + cBase + b_nq[r]);
            }
        }

#pragma unroll
        for (int kf = 0; kf < 4; kf++) {
            uint32_t aF[4][4];
#pragma unroll
            for (int mf = 0; mf < 4; mf++) {
                uint4 q = *(const uint4*)(As + bufA +
                            (((wr * 4 + mf) * 4 + kf) * 128) + lane * 4);
                aF[mf][0] = q.x; aF[mf][1] = q.y; aF[mf][2] = q.z; aF[mf][3] = q.w;
            }
            uint32_t bF[4][2];
            const uint32_t* bk0 = Bs + bufB + (kf * 8 + tig) * BPAD;
            const uint32_t* bk1 = bk0 + 4 * BPAD;
#pragma unroll
            for (int nf = 0; nf < 4; nf++) {
                const int nc = n0 + nf * 8 + gID;
                bF[nf][0] = bk0[nc];
                bF[nf][1] = bk1[nc];
            }
#pragma unroll
            for (int mf = 0; mf < 4; mf++)
#pragma unroll
                for (int nf = 0; nf < 4; nf++)
                    mma_tf32(acc[mf][nf], aF[mf], bF[nf]);
        }

        if (more) {
            const int nbA = (bufA ^ ABUF);
            const int nbB = (bufB ^ BBUF);
#pragma unroll
            for (int r = 0; r < 4; r++) {
                uint32_t* p = As + nbA + a_off[r];
                p[0]  = f2tf(pa[r].x); p[4]  = f2tf(pa[r].y);
                p[8]  = f2tf(pa[r].z); p[12] = f2tf(pa[r].w);
                uint4 bv = make_uint4(f2tf(pb[r].x), f2tf(pb[r].y),
                                      f2tf(pb[r].z), f2tf(pb[r].w));
                *(uint4*)(Bs + nbB + b_kr[r] * BPAD + b_nq[r]) = bv;
            }
        }
        __syncthreads();
    }

    // ---- epilogue ----
#pragma unroll
    for (int mf = 0; mf < 4; mf++) {
#pragma unroll
        for (int nf = 0; nf < 4; nf++) {
            const int row = rBase + wr * 64 + mf * 16 + gID;
            const int col = cBase + n0 + nf * 8 + tig * 2;
            float* p0 = C + (size_t)row * N + col;
            float* p1 = C + (size_t)(row + 8) * N + col;
            if (EPI == 0) {
                *(float2*)p0 = make_float2(acc[mf][nf][0], acc[mf][nf][1]);
                *(float2*)p1 = make_float2(acc[mf][nf][2], acc[mf][nf][3]);
            } else if (EPI == 2) {
                *(uint2*)p0 = make_uint2(f2tf(acc[mf][nf][0]), f2tf(acc[mf][nf][1]));
                *(uint2*)p1 = make_uint2(f2tf(acc[mf][nf][2]), f2tf(acc[mf][nf][3]));
            } else {
                // RoPE pair (even,odd) = (c0,c1); fold scale; tf32-round.
                const int pr = (col & (PHD - 1)) >> 1;
                const int s0 = row & (PS - 1);
                const int s1 = (row + 8) & (PS - 1);
                const float c0 = fc[s0 * 64 + pr], sn0 = fs[s0 * 64 + pr];
                const float c1 = fc[s1 * 64 + pr], sn1 = fs[s1 * 64 + pr];
                const float r0 = (acc[mf][nf][0] * c0 - acc[mf][nf][1] * sn0) * scale;
                const float i0 = (acc[mf][nf][0] * sn0 + acc[mf][nf][1] * c0) * scale;
                const float r1 = (acc[mf][nf][2] * c1 - acc[mf][nf][3] * sn1) * scale;
                const float i1 = (acc[mf][nf][2] * sn1 + acc[mf][nf][3] * c1) * scale;
                *(uint2*)p0 = make_uint2(f2tf(r0), f2tf(i0));
                *(uint2*)p1 = make_uint2(f2tf(r1), f2tf(i1));
            }
        }
    }
}

// ---------------------------------------------------------------------------
// Tensor-core causal flash attention (unchanged from round 8).
// ---------------------------------------------------------------------------
#define BQ 128
#define BK 64
#define KPAD 132
#define VPAD 136
#define PPAD 68

__global__ __launch_bounds__(256, 1)
void flash_attn_tc(const float* __restrict__ Q, const float* __restrict__ K,
                   const float* __restrict__ V, float* __restrict__ O) {
    extern __shared__ float sm[];
    float* Ks = sm;                    // [64][132]
    float* Vs = Ks + BK * KPAD;        // [64][136]
    float* Ps = Vs + BK * VPAD;        // [128][68]

    const int tid  = threadIdx.x;
    const int lane = tid & 31;
    const int wid  = tid >> 5;
    const int gID  = lane >> 2;
    const int tig  = lane & 3;
    const int qb   = blockIdx.x;
    const int h    = blockIdx.y;
    const int b    = blockIdx.z;
    const int kvh  = h >> 2;
    const int m0   = wid * 16;
    const int qRow0 = b * PS + qb * BQ;

    uint32_t aQ[16][4];
    {
        const float* Qg = Q + (size_t)(qRow0 + m0) * QCOLS + h * PHD;
#pragma unroll
        for (int kb = 0; kb < 16; kb++) {
            const int c = kb * 8 + tig;
            aQ[kb][0] = __float_as_uint(Qg[(size_t)gID       * QCOLS + c    ]);
            aQ[kb][1] = __float_as_uint(Qg[(size_t)(gID + 8) * QCOLS + c    ]);
            aQ[kb][2] = __float_as_uint(Qg[(size_t)gID       * QCOLS + c + 4]);
            aQ[kb][3] = __float_as_uint(Qg[(size_t)(gID + 8) * QCOLS + c + 4]);
        }
    }

    float oAcc[16][4];
#pragma unroll
    for (int nf = 0; nf < 16; nf++)
#pragma unroll
        for (int r = 0; r < 4; r++) oAcc[nf][r] = 0.f;
    float m_i[2] = {-1e30f, -1e30f};
    float l_i[2] = {0.f, 0.f};

    const int nkt = 2 * qb + 2;
    for (int kt = 0; kt < nkt; kt++) {
        __syncthreads();
        {
            const int kRow0 = b * PS + kt * BK;
            const float* Kg = K + (size_t)kRow0 * KVCOLS + kvh * PHD;
            const float* Vg = V + (size_t)kRow0 * KVCOLS + kvh * PHD;
#pragma unroll
            for (int r = 0; r < 8; r++) {
                int t  = tid + r * 256;
                int j  = t >> 5;
                int c4 = (t & 31) * 4;
                *(float4*)(&Ks[j * KPAD + c4]) =
                    *(const float4*)(Kg + (size_t)j * KVCOLS + c4);
                *(float4*)(&Vs[j * VPAD + c4]) =
                    *(const float4*)(Vg + (size_t)j * KVCOLS + c4);
            }
        }
        __syncthreads();

        float sAcc[8][4];
#pragma unroll
        for (int nf = 0; nf < 8; nf++)
#pragma unroll
            for (int r = 0; r < 4; r++) sAcc[nf][r] = 0.f;

#pragma unroll
        for (int kb = 0; kb < 16; kb++) {
            const int kc = kb * 8 + tig;
#pragma unroll
            for (int nf = 0; nf < 8; nf++) {
                uint32_t bK[2];
                bK[0] = __float_as_uint(Ks[(nf * 8 + gID) * KPAD + kc    ]);
                bK[1] = __float_as_uint(Ks[(nf * 8 + gID) * KPAD + kc + 4]);
                mma_tf32(sAcc[nf], aQ[kb], bK);
            }
        }

        if (kt >= 2 * qb) {
            const int r0 = qb * BQ + m0 + gID;
            const int r1 = r0 + 8;
            const int cb = kt * BK + 2 * tig;
#pragma unroll
            for (int nf = 0; nf < 8; nf++) {
                const int c0 = cb + nf * 8;
                if (c0     > r0) sAcc[nf][0] = -1e30f;
                if (c0 + 1 > r0) sAcc[nf][1] = -1e30f;
                if (c0     > r1) sAcc[nf][2] = -1e30f;
                if (c0 + 1 > r1) sAcc[nf][3] = -1e30f;
            }
        }

        float mx0 = -1e30f, mx1 = -1e30f;
#pragma unroll
        for (int nf = 0; nf < 8; nf++) {
            mx0 = fmaxf(mx0, fmaxf(sAcc[nf][0], sAcc[nf][1]));
            mx1 = fmaxf(mx1, fmaxf(sAcc[nf][2], sAcc[nf][3]));
        }
        mx0 = fmaxf(mx0, __shfl_xor_sync(0xffffffffu, mx0, 1));
        mx0 = fmaxf(mx0, __shfl_xor_sync(0xffffffffu, mx0, 2));
        mx1 = fmaxf(mx1, __shfl_xor_sync(0xffffffffu, mx1, 1));
        mx1 = fmaxf(mx1, __shfl_xor_sync(0xffffffffu, mx1, 2));

        const float mn0 = fmaxf(m_i[0], mx0);
        const float mn1 = fmaxf(m_i[1], mx1);
        const float al0 = __expf(m_i[0] - mn0);
        const float al1 = __expf(m_i[1] - mn1);

        float rs0 = 0.f, rs1 = 0.f;
#pragma unroll
        for (int nf = 0; nf < 8; nf++) {
            sAcc[nf][0] = __expf(sAcc[nf][0] - mn0);
            sAcc[nf][1] = __expf(sAcc[nf][1] - mn0);
            sAcc[nf][2] = __expf(sAcc[nf][2] - mn1);
            sAcc[nf][3] = __expf(sAcc[nf][3] - mn1);
            rs0 += sAcc[nf][0] + sAcc[nf][1];
            rs1 += sAcc[nf][2] + sAcc[nf][3];
        }
        rs0 += __shfl_xor_sync(0xffffffffu, rs0, 1);
        rs0 += __shfl_xor_sync(0xffffffffu, rs0, 2);
        rs1 += __shfl_xor_sync(0xffffffffu, rs1, 1);
        rs1 += __shfl_xor_sync(0xffffffffu, rs1, 2);

        l_i[0] = l_i[0] * al0 + rs0;
        l_i[1] = l_i[1] * al1 + rs1;
        m_i[0] = mn0;
        m_i[1] = mn1;

#pragma unroll
        for (int nf = 0; nf < 16; nf++) {
            oAcc[nf][0] *= al0; oAcc[nf][1] *= al0;
            oAcc[nf][2] *= al1; oAcc[nf][3] *= al1;
        }

#pragma unroll
        for (int nf = 0; nf < 8; nf++) {
            const int col = nf * 8 + 2 * tig;
            *(uint2*)(&Ps[(m0 + gID    ) * PPAD + col]) =
                make_uint2(f2tf(sAcc[nf][0]), f2tf(sAcc[nf][1]));
            *(uint2*)(&Ps[(m0 + gID + 8) * PPAD + col]) =
                make_uint2(f2tf(sAcc[nf][2]), f2tf(sAcc[nf][3]));
        }
        __syncwarp();

#pragma unroll
        for (int kb = 0; kb < 8; kb++) {
            const int kc = kb * 8 + tig;
            uint32_t aP[4];
            aP[0] = __float_as_uint(Ps[(m0 + gID    ) * PPAD + kc    ]);
            aP[1] = __float_as_uint(Ps[(m0 + gID + 8) * PPAD + kc    ]);
            aP[2] = __float_as_uint(Ps[(m0 + gID    ) * PPAD + kc + 4]);
            aP[3] = __float_as_uint(Ps[(m0 + gID + 8) * PPAD + kc + 4]);
#pragma unroll
            for (int nf = 0; nf < 16; nf++) {
                uint32_t bV[2];
                bV[0] = __float_as_uint(Vs[(kc    ) * VPAD + nf * 8 + gID]);
                bV[1] = __float_as_uint(Vs[(kc + 4) * VPAD + nf * 8 + gID]);
                mma_tf32(oAcc[nf], aP, bV);
            }
        }
        __syncwarp();
    }

    const float il0 = 1.f / l_i[0];
    const float il1 = 1.f / l_i[1];
    float* Og = O + (size_t)(qRow0 + m0) * QCOLS + h * PHD;
#pragma unroll
    for (int nf = 0; nf < 16; nf++) {
        const int col = nf * 8 + 2 * tig;
        *(float2*)(Og + (size_t)gID       * QCOLS + col) =
            make_float2(oAcc[nf][0] * il0, oAcc[nf][1] * il0);
        *(float2*)(Og + (size_t)(gID + 8) * QCOLS + col) =
            make_float2(oAcc[nf][2] * il1, oAcc[nf][3] * il1);
    }
}

// ---------------------------------------------------------------------------
// Launch
// ---------------------------------------------------------------------------
extern "C" void kernel_launch(void* const* d_in, const int* in_sizes, int n_in,
                              void* d_out, int out_size) {
    (void)in_sizes; (void)n_in; (void)out_size;

    const float* x  = (const float*)d_in[0];   // [B,S,D]
    const float* fc = (const float*)d_in[1];   // [S, HD/2]
    const float* fs = (const float*)d_in[2];   // [S, HD/2]
    const float* Wq = (const float*)d_in[3];   // [D, H*HD]
    const float* Wk = (const float*)d_in[4];   // [D, KVH*HD]
    const float* Wv = (const float*)d_in[5];   // [D, KVH*HD]
    const float* Wo = (const float*)d_in[6];   // [H*HD, D]
    float* out = (float*)d_out;                // [B,S,D]

    float *Qb, *Kb, *Vb, *Ob;
    cudaGetSymbolAddress((void**)&Qb, g_Q);
    cudaGetSymbolAddress((void**)&Kb, g_K);
    cudaGetSymbolAddress((void**)&Vb, g_V);
    cudaGetSymbolAddress((void**)&Ob, g_O);

    cudaFuncSetAttribute(tf32gemm<0>, cudaFuncAttributeMaxDynamicSharedMemorySize, GSMEM);
    cudaFuncSetAttribute(tf32gemm<1>, cudaFuncAttributeMaxDynamicSharedMemorySize, GSMEM);
    cudaFuncSetAttribute(tf32gemm<2>, cudaFuncAttributeMaxDynamicSharedMemorySize, GSMEM);

    const float qscale = 0.08838834764831845f;   // 1/sqrt(128)

    // 1) QKV projections with fused RoPE/scale/round epilogues
    tf32gemm<1><<<dim3(QCOLS/TBN,  ROWS/TBM), 256, GSMEM>>>(
        x, Wq, Qb, ROWS, QCOLS,  PD, fc, fs, qscale);
    tf32gemm<1><<<dim3(KVCOLS/TBN, ROWS/TBM), 256, GSMEM>>>(
        x, Wk, Kb, ROWS, KVCOLS, PD, fc, fs, 1.0f);
    tf32gemm<2><<<dim3(KVCOLS/TBN, ROWS/TBM), 256, GSMEM>>>(
        x, Wv, Vb, ROWS, KVCOLS, PD, nullptr, nullptr, 1.0f);

    // 2) Tensor-core causal flash attention
    {
        size_t smem = (size_t)(BK * KPAD + BK * VPAD + BQ * PPAD) * sizeof(float);
        cudaFuncSetAttribute(flash_attn_tc,
                             cudaFuncAttributeMaxDynamicSharedMemorySize, (int)smem);
        flash_attn_tc<<<dim3(PS/BQ, PH, PB), 256, smem>>>(Qb, Kb, Vb, Ob);
    }

    // 3) Output projection -> d_out
    tf32gemm<0><<<dim3(PD/TBN, ROWS/TBM), 256, GSMEM>>>(
        Ob, Wo, out, ROWS, PD, QCOLS, nullptr, nullptr, 1.0f);
}